// round 1
// baseline (speedup 1.0000x reference)
#include <cuda_runtime.h>
#include <cstdint>

// Shapes (fixed for this problem)
#define Bk 8
#define Lk 4096
#define Hk 16
#define Ek 64
#define BH (Bk*Hk)          // 128
#define ROWSTRIDE (Hk*Ek)   // 1024 floats between consecutive l

// Scratch (no allocations allowed): per-head KV (64x64) and ksum (64)
__device__ __align__(16) float g_kv[BH*Ek*Ek];    // 2 MB
__device__ __align__(16) float g_ksum[BH*Ek];     // 32 KB

typedef unsigned long long ull;

__device__ __forceinline__ ull pack2(float lo, float hi){
    ull r; asm("mov.b64 %0,{%1,%2};" : "=l"(r) : "f"(lo), "f"(hi)); return r;
}
__device__ __forceinline__ float2 unpk2(ull v){
    float2 r; asm("mov.b64 {%0,%1},%2;" : "=f"(r.x), "=f"(r.y) : "l"(v)); return r;
}
__device__ __forceinline__ ull fma2(ull a, ull b, ull c){
    ull d; asm("fma.rn.f32x2 %0,%1,%2,%3;" : "=l"(d) : "l"(a), "l"(b), "l"(c)); return d;
}
__device__ __forceinline__ float ex2(float x){
    float y; asm("ex2.approx.f32 %0,%1;" : "=f"(y) : "f"(x)); return y;
}

// ---------------------------------------------------------------------------
// Zero scratch each launch (graph replays!)
// ---------------------------------------------------------------------------
__global__ void zero_kernel(){
    int i = blockIdx.x*blockDim.x + threadIdx.x;
    float4 z = make_float4(0.f,0.f,0.f,0.f);
    if (i < BH*Ek*Ek/4) ((float4*)g_kv)[i] = z;
    if (i < BH*Ek/4)    ((float4*)g_ksum)[i] = z;
}

// ---------------------------------------------------------------------------
// Pass 1: k-softmax + KV / ksum accumulation.
// grid = 128 bh * 16 chunks = 2048 blocks, 128 threads.
// Each block: 256 rows. Warp-per-row softmax into shared, then all threads
// accumulate a (2e x 16d) KV tile in registers via f32x2 FMA; atomicAdd out.
// ---------------------------------------------------------------------------
#define P1_THREADS 128
#define P1_TILE 16
#define P1_CHUNK 256

__global__ __launch_bounds__(P1_THREADS)
void pass1_kernel(const float* __restrict__ kin, const float* __restrict__ vin,
                  const float* __restrict__ dp)
{
    __shared__ float ks[P1_TILE][Ek];
    __shared__ float vs[P1_TILE][Ek];

    const int tid  = threadIdx.x;
    const int lane = tid & 31;
    const int warp = tid >> 5;
    const int blk  = blockIdx.x;
    const int bh    = blk >> 4;     // 4096/256 = 16 chunks
    const int chunk = blk & 15;
    const int b = bh >> 4, h = bh & 15;
    const long base_bh = (long)b * Lk * ROWSTRIDE + (long)h * Ek;
    const int l0 = chunk * P1_CHUNK;

    const float d1   = dp[0];
    const float temp = log1pf(__expf(d1));          // softplus(delta1)
    const float c    = 1.44269504088896340736f / temp; // log2(e)/temp

    const int p  = tid >> 2;        // e-pair index: e0 = 2p
    const int d0 = (tid & 3) * 16;  // 16-wide d group

    ull acc[16];
    #pragma unroll
    for (int j = 0; j < 16; j++) acc[j] = 0ULL;
    float2 lks = make_float2(0.f, 0.f);

    for (int t = 0; t < P1_CHUNK / P1_TILE; t++) {
        __syncthreads();
        // stage 16 rows: warp w handles rows t*16 + 4w .. +3
        #pragma unroll
        for (int i = 0; i < 4; i++) {
            const int rloc = warp * 4 + i;
            const int l = l0 + t * P1_TILE + rloc;
            const float2* krow = (const float2*)(kin + base_bh + (long)l * ROWSTRIDE);
            const float2* vrow = (const float2*)(vin + base_bh + (long)l * ROWSTRIDE);
            float2 kv2 = krow[lane];
            float2 vv2 = vrow[lane];
            float x0 = kv2.x < 0.f ? -20.f : kv2.x;
            float x1 = kv2.y < 0.f ? -20.f : kv2.y;
            float e0 = ex2(x0 * c), e1 = ex2(x1 * c);
            float s = e0 + e1;
            #pragma unroll
            for (int o = 16; o > 0; o >>= 1) s += __shfl_xor_sync(0xffffffffu, s, o);
            float rinv = 1.f / s;
            e0 *= rinv; e1 *= rinv;
            *(float2*)&ks[rloc][2*lane] = make_float2(e0, e1);
            *(float2*)&vs[rloc][2*lane] = vv2;
            lks.x += e0; lks.y += e1;
        }
        __syncthreads();
        // accumulate 16 rows into register KV tile
        #pragma unroll
        for (int r = 0; r < P1_TILE; r++) {
            float2 kk = *(const float2*)&ks[r][2*p];
            ull ee0 = pack2(kk.x, kk.x);
            ull ee1 = pack2(kk.y, kk.y);
            const ulonglong2* vp = (const ulonglong2*)&vs[r][d0]; // 4 x 16B
            #pragma unroll
            for (int j = 0; j < 4; j++) {
                ulonglong2 u = vp[j];
                acc[2*j]     = fma2(ee0, u.x, acc[2*j]);
                acc[2*j+1]   = fma2(ee0, u.y, acc[2*j+1]);
                acc[8+2*j]   = fma2(ee1, u.x, acc[8+2*j]);
                acc[8+2*j+1] = fma2(ee1, u.y, acc[8+2*j+1]);
            }
        }
    }

    float* kvdst = g_kv + (long)bh * Ek * Ek;
    #pragma unroll
    for (int j = 0; j < 8; j++) {
        float2 a0 = unpk2(acc[j]);
        float2 a1 = unpk2(acc[8+j]);
        atomicAdd(&kvdst[(2*p)  *Ek + d0 + 2*j    ], a0.x);
        atomicAdd(&kvdst[(2*p)  *Ek + d0 + 2*j + 1], a0.y);
        atomicAdd(&kvdst[(2*p+1)*Ek + d0 + 2*j    ], a1.x);
        atomicAdd(&kvdst[(2*p+1)*Ek + d0 + 2*j + 1], a1.y);
    }
    atomicAdd(&g_ksum[bh*Ek + 2*lane],     lks.x);
    atomicAdd(&g_ksum[bh*Ek + 2*lane + 1], lks.y);
}

// ---------------------------------------------------------------------------
// Pass 2: q-softmax numerator + out = (eq @ KV) / (eq.ksum + eps*sq).
// grid = 128 bh * 32 chunks = 4096 blocks, 128 threads, thread-per-row.
// eq staged in padded shared (stride 65 -> conflict-free), KV broadcast LDS.
// ---------------------------------------------------------------------------
#define P2_THREADS 128
#define P2_ROWS 128

__global__ __launch_bounds__(P2_THREADS)
void pass2_kernel(const float* __restrict__ qin, float* __restrict__ out,
                  const float* __restrict__ dp)
{
    __shared__ float kvs[Ek*Ek];              // 16 KB
    __shared__ float kss[Ek];
    __shared__ float eqs[P2_THREADS][Ek+1];   // 65-stride, ~33 KB

    const int tid = threadIdx.x;
    const int blk = blockIdx.x;
    const int bh    = blk >> 5;   // 4096/128 = 32 chunks
    const int chunk = blk & 31;
    const int b = bh >> 4, h = bh & 15;

    // load KV + ksum
    {
        const float4* src = (const float4*)(g_kv + (long)bh * Ek * Ek);
        float4* dst = (float4*)kvs;
        #pragma unroll
        for (int j = 0; j < 8; j++) dst[tid + j*128] = src[tid + j*128];
        if (tid < Ek) kss[tid] = g_ksum[bh*Ek + tid];
    }
    const float d1   = dp[0];
    const float temp = log1pf(__expf(d1));
    const float c    = 1.44269504088896340736f / temp;
    __syncthreads();

    const int l = chunk * P2_ROWS + tid;
    const float* qrow = qin + ((long)b * Lk + l) * ROWSTRIDE + (long)h * Ek;
    float*       orow = out + ((long)b * Lk + l) * ROWSTRIDE + (long)h * Ek;

    float sq = 0.f;
    #pragma unroll
    for (int j = 0; j < 16; j++) {
        float4 qv = ((const float4*)qrow)[j];
        float e0 = ex2((qv.x < 0.f ? -20.f : qv.x) * c);
        float e1 = ex2((qv.y < 0.f ? -20.f : qv.y) * c);
        float e2 = ex2((qv.z < 0.f ? -20.f : qv.z) * c);
        float e3 = ex2((qv.w < 0.f ? -20.f : qv.w) * c);
        eqs[tid][4*j]   = e0;
        eqs[tid][4*j+1] = e1;
        eqs[tid][4*j+2] = e2;
        eqs[tid][4*j+3] = e3;
        sq += e0 + e1 + e2 + e3;
    }

    float dn = 1e-6f * sq;
    #pragma unroll 8
    for (int e = 0; e < Ek; e++) dn += eqs[tid][e] * kss[e];
    const float inv = 1.f / dn;

    #pragma unroll
    for (int half = 0; half < 2; half++) {
        const int d0 = half * 32;
        ull acc[16];
        #pragma unroll
        for (int j = 0; j < 16; j++) acc[j] = 0ULL;
        #pragma unroll 8
        for (int e = 0; e < Ek; e++) {
            float eqv = eqs[tid][e];
            ull ee = pack2(eqv, eqv);
            const ulonglong2* kp = (const ulonglong2*)&kvs[e*Ek + d0]; // 8 x 16B
            #pragma unroll
            for (int j = 0; j < 8; j++) {
                ulonglong2 u = kp[j];
                acc[2*j]   = fma2(ee, u.x, acc[2*j]);
                acc[2*j+1] = fma2(ee, u.y, acc[2*j+1]);
            }
        }
        #pragma unroll
        for (int j = 0; j < 8; j++) {
            float2 a = unpk2(acc[2*j]);
            float2 b2 = unpk2(acc[2*j+1]);
            ((float4*)orow)[half*8 + j] =
                make_float4(a.x*inv, a.y*inv, b2.x*inv, b2.y*inv);
        }
    }
}

// ---------------------------------------------------------------------------
extern "C" void kernel_launch(void* const* d_in, const int* in_sizes, int n_in,
                              void* d_out, int out_size)
{
    const float* q  = (const float*)d_in[0];
    const float* k  = (const float*)d_in[1];
    const float* v  = (const float*)d_in[2];
    const float* d1 = (const float*)d_in[3];
    float* out = (float*)d_out;

    zero_kernel<<<512, 256>>>();
    pass1_kernel<<<BH * (Lk / P1_CHUNK), P1_THREADS>>>(k, v, d1);
    pass2_kernel<<<BH * (Lk / P2_ROWS), P2_THREADS>>>(q, out, d1);
}

// round 2
// speedup vs baseline: 1.4969x; 1.4969x over previous
#include <cuda_runtime.h>

// Shapes (fixed)
#define Bk 8
#define Lk 4096
#define Hk 16
#define Ek 64
#define BH (Bk*Hk)          // 128
#define RS (Hk*Ek)          // 1024 floats between consecutive l

// Scratch (no allocations allowed)
__device__ __align__(16) float g_kv[BH*Ek*Ek];    // 2 MB
__device__ __align__(16) float g_ksum[BH*Ek];     // 32 KB

typedef unsigned long long ull;

__device__ __forceinline__ ull pack2(float lo, float hi){
    ull r; asm("mov.b64 %0,{%1,%2};" : "=l"(r) : "f"(lo), "f"(hi)); return r;
}
__device__ __forceinline__ float2 unpk2(ull v){
    float2 r; asm("mov.b64 {%0,%1},%2;" : "=f"(r.x), "=f"(r.y) : "l"(v)); return r;
}
__device__ __forceinline__ ull fma2(ull a, ull b, ull c){
    ull d; asm("fma.rn.f32x2 %0,%1,%2,%3;" : "=l"(d) : "l"(a), "l"(b), "l"(c)); return d;
}
__device__ __forceinline__ float ex2(float x){
    float y; asm("ex2.approx.f32 %0,%1;" : "=f"(y) : "f"(x)); return y;
}

// ---------------------------------------------------------------------------
// Zero scratch each launch (graph replays!)
// ---------------------------------------------------------------------------
__global__ void zero_kernel(){
    int i = blockIdx.x*blockDim.x + threadIdx.x;
    float4 z = make_float4(0.f,0.f,0.f,0.f);
    if (i < BH*Ek*Ek/4) ((float4*)g_kv)[i] = z;
    if (i < BH*Ek/4)    ((float4*)g_ksum)[i] = z;
}

// ---------------------------------------------------------------------------
// Pass 1: k-softmax + KV / ksum accumulation.
// grid = 128 bh * 16 chunks = 2048 blocks, 128 threads.
// Warp-per-row softmax into shared; register tile 4e x 8d per thread:
// 3 LDS.128 per 16 fma2.
// ---------------------------------------------------------------------------
#define P1_THREADS 128
#define P1_TILE 16
#define P1_CHUNK 256

__global__ __launch_bounds__(P1_THREADS)
void pass1_kernel(const float* __restrict__ kin, const float* __restrict__ vin,
                  const float* __restrict__ dp)
{
    __shared__ float ks[P1_TILE][Ek];
    __shared__ float vs[P1_TILE][Ek];

    const int tid  = threadIdx.x;
    const int lane = tid & 31;
    const int warp = tid >> 5;
    const int blk  = blockIdx.x;
    const int bh    = blk >> 4;
    const int chunk = blk & 15;
    const int b = bh >> 4, h = bh & 15;
    const long base_bh = (long)b * Lk * RS + (long)h * Ek;
    const int l0 = chunk * P1_CHUNK;

    const float d1   = dp[0];
    const float temp = log1pf(__expf(d1));             // softplus(delta1)
    const float c    = 1.44269504088896340736f / temp; // log2(e)/temp

    const int e0 = (tid & 15) * 4;   // 16 e-groups of 4
    const int d0 = (tid >> 4) * 8;   // 8 d-groups of 8

    ull acc[16];
    #pragma unroll
    for (int j = 0; j < 16; j++) acc[j] = 0ULL;
    float2 lks = make_float2(0.f, 0.f);

    for (int t = 0; t < P1_CHUNK / P1_TILE; t++) {
        __syncthreads();
        // stage 16 rows: warp w handles rows 4w..4w+3
        #pragma unroll
        for (int i = 0; i < 4; i++) {
            const int rloc = warp * 4 + i;
            const int l = l0 + t * P1_TILE + rloc;
            float2 kk = ((const float2*)(kin + base_bh + (long)l * RS))[lane];
            float2 vv = ((const float2*)(vin + base_bh + (long)l * RS))[lane];
            float x0 = kk.x < 0.f ? -20.f : kk.x;
            float x1 = kk.y < 0.f ? -20.f : kk.y;
            float q0 = ex2(x0 * c), q1 = ex2(x1 * c);
            float s = q0 + q1;
            #pragma unroll
            for (int o = 16; o > 0; o >>= 1) s += __shfl_xor_sync(0xffffffffu, s, o);
            float rinv = 1.f / s;
            q0 *= rinv; q1 *= rinv;
            *(float2*)&ks[rloc][2*lane] = make_float2(q0, q1);
            *(float2*)&vs[rloc][2*lane] = vv;
            lks.x += q0; lks.y += q1;
        }
        __syncthreads();
        // accumulate 16 rows: per row, 4e x 8d register tile
        #pragma unroll
        for (int r = 0; r < P1_TILE; r++) {
            float4 a = *(const float4*)&ks[r][e0];
            ulonglong2 b0 = ((const ulonglong2*)&vs[r][d0])[0];
            ulonglong2 b1 = ((const ulonglong2*)&vs[r][d0])[1];
            ull ea;
            ea = pack2(a.x, a.x);
            acc[0]  = fma2(ea, b0.x, acc[0]);  acc[1]  = fma2(ea, b0.y, acc[1]);
            acc[2]  = fma2(ea, b1.x, acc[2]);  acc[3]  = fma2(ea, b1.y, acc[3]);
            ea = pack2(a.y, a.y);
            acc[4]  = fma2(ea, b0.x, acc[4]);  acc[5]  = fma2(ea, b0.y, acc[5]);
            acc[6]  = fma2(ea, b1.x, acc[6]);  acc[7]  = fma2(ea, b1.y, acc[7]);
            ea = pack2(a.z, a.z);
            acc[8]  = fma2(ea, b0.x, acc[8]);  acc[9]  = fma2(ea, b0.y, acc[9]);
            acc[10] = fma2(ea, b1.x, acc[10]); acc[11] = fma2(ea, b1.y, acc[11]);
            ea = pack2(a.w, a.w);
            acc[12] = fma2(ea, b0.x, acc[12]); acc[13] = fma2(ea, b0.y, acc[13]);
            acc[14] = fma2(ea, b1.x, acc[14]); acc[15] = fma2(ea, b1.y, acc[15]);
        }
    }

    float* kvdst = g_kv + (long)bh * Ek * Ek;
    #pragma unroll
    for (int e = 0; e < 4; e++) {
        #pragma unroll
        for (int j = 0; j < 4; j++) {
            float2 p = unpk2(acc[e*4 + j]);
            atomicAdd(&kvdst[(e0+e)*Ek + d0 + 2*j    ], p.x);
            atomicAdd(&kvdst[(e0+e)*Ek + d0 + 2*j + 1], p.y);
        }
    }
    atomicAdd(&g_ksum[bh*Ek + 2*lane],     lks.x);
    atomicAdd(&g_ksum[bh*Ek + 2*lane + 1], lks.y);
}

// ---------------------------------------------------------------------------
// Pass 2: q-softmax numerator + out = (eq @ KV) / (eq.ksum + eps*sq).
// grid = 128 bh * 64 chunks = 8192 blocks, 128 threads, 64 rows per block.
// Softmax: half-row per thread, pair combine via shfl. GEMM: 4 rows x 8 cols
// register tile per thread, eq transposed in smem (stride 68, aligned).
// ---------------------------------------------------------------------------
#define P2_THREADS 128
#define P2_ROWS 64
#define EQT_S 68

__global__ __launch_bounds__(P2_THREADS)
void pass2_kernel(const float* __restrict__ qin, float* __restrict__ out,
                  const float* __restrict__ dp)
{
    __shared__ float kvs[Ek][Ek];       // 16 KB
    __shared__ float eqT[Ek][EQT_S];    // 17.4 KB
    __shared__ float kss[Ek];
    __shared__ float invs[P2_ROWS];

    const int tid = threadIdx.x;
    const int blk = blockIdx.x;
    const int bh    = blk >> 6;
    const int chunk = blk & 63;
    const int b = bh >> 4, h = bh & 15;

    // load KV + ksum
    {
        const float4* src = (const float4*)(g_kv + (long)bh * Ek * Ek);
        float4* dst = (float4*)kvs;
        #pragma unroll
        for (int j = 0; j < 8; j++) dst[tid + j*128] = src[tid + j*128];
        if (tid < 16) ((float4*)kss)[tid] = ((const float4*)(g_ksum + bh*Ek))[tid];
    }
    const float d1   = dp[0];
    const float temp = log1pf(__expf(d1));
    const float c    = 1.44269504088896340736f / temp;
    __syncthreads();

    // softmax numerator: half-row per thread (row = tid>>1, half = tid&1)
    {
        const int lrow = tid >> 1;
        const int hh   = tid & 1;
        const int l = chunk * P2_ROWS + lrow;
        const float4* qrow = (const float4*)(qin + ((long)b*Lk + l)*RS + h*Ek + hh*32);
        float sq = 0.f, dn = 0.f;
        #pragma unroll
        for (int j = 0; j < 8; j++) {
            float4 qv = qrow[j];
            int e = hh*32 + 4*j;
            float v0 = ex2((qv.x < 0.f ? -20.f : qv.x) * c);
            float v1 = ex2((qv.y < 0.f ? -20.f : qv.y) * c);
            float v2 = ex2((qv.z < 0.f ? -20.f : qv.z) * c);
            float v3 = ex2((qv.w < 0.f ? -20.f : qv.w) * c);
            eqT[e  ][lrow] = v0;
            eqT[e+1][lrow] = v1;
            eqT[e+2][lrow] = v2;
            eqT[e+3][lrow] = v3;
            sq += v0 + v1 + v2 + v3;
            dn += v0*kss[e] + v1*kss[e+1] + v2*kss[e+2] + v3*kss[e+3];
        }
        sq += __shfl_xor_sync(0xffffffffu, sq, 1);
        dn += __shfl_xor_sync(0xffffffffu, dn, 1);
        if (hh == 0) invs[lrow] = 1.f / (dn + 1e-6f * sq);
    }
    __syncthreads();

    // GEMM: out[64 rows][64 cols], thread tile 4 rows x 8 cols
    const int r0 = (tid >> 3) * 4;   // 16 row-groups of 4
    const int c0 = (tid & 7) * 8;    // 8 col-groups of 8

    ull acc[16];
    #pragma unroll
    for (int j = 0; j < 16; j++) acc[j] = 0ULL;

    #pragma unroll 8
    for (int e = 0; e < Ek; e++) {
        float4 a = *(const float4*)&eqT[e][r0];
        ulonglong2 b0 = ((const ulonglong2*)&kvs[e][c0])[0];
        ulonglong2 b1 = ((const ulonglong2*)&kvs[e][c0])[1];
        ull ea;
        ea = pack2(a.x, a.x);
        acc[0]  = fma2(ea, b0.x, acc[0]);  acc[1]  = fma2(ea, b0.y, acc[1]);
        acc[2]  = fma2(ea, b1.x, acc[2]);  acc[3]  = fma2(ea, b1.y, acc[3]);
        ea = pack2(a.y, a.y);
        acc[4]  = fma2(ea, b0.x, acc[4]);  acc[5]  = fma2(ea, b0.y, acc[5]);
        acc[6]  = fma2(ea, b1.x, acc[6]);  acc[7]  = fma2(ea, b1.y, acc[7]);
        ea = pack2(a.z, a.z);
        acc[8]  = fma2(ea, b0.x, acc[8]);  acc[9]  = fma2(ea, b0.y, acc[9]);
        acc[10] = fma2(ea, b1.x, acc[10]); acc[11] = fma2(ea, b1.y, acc[11]);
        ea = pack2(a.w, a.w);
        acc[12] = fma2(ea, b0.x, acc[12]); acc[13] = fma2(ea, b0.y, acc[13]);
        acc[14] = fma2(ea, b1.x, acc[14]); acc[15] = fma2(ea, b1.y, acc[15]);
    }

    // epilogue: scale + store (coalesced: 8 lanes cover one 256B row span)
    #pragma unroll
    for (int r = 0; r < 4; r++) {
        const int lr = chunk * P2_ROWS + r0 + r;
        const float iv = invs[r0 + r];
        float* orow = out + ((long)b*Lk + lr)*RS + h*Ek + c0;
        float2 p0 = unpk2(acc[r*4 + 0]);
        float2 p1 = unpk2(acc[r*4 + 1]);
        float2 p2 = unpk2(acc[r*4 + 2]);
        float2 p3 = unpk2(acc[r*4 + 3]);
        ((float4*)orow)[0] = make_float4(p0.x*iv, p0.y*iv, p1.x*iv, p1.y*iv);
        ((float4*)orow)[1] = make_float4(p2.x*iv, p2.y*iv, p3.x*iv, p3.y*iv);
    }
}

// ---------------------------------------------------------------------------
extern "C" void kernel_launch(void* const* d_in, const int* in_sizes, int n_in,
                              void* d_out, int out_size)
{
    const float* q  = (const float*)d_in[0];
    const float* k  = (const float*)d_in[1];
    const float* v  = (const float*)d_in[2];
    const float* d1 = (const float*)d_in[3];
    float* out = (float*)d_out;

    zero_kernel<<<512, 256>>>();
    pass1_kernel<<<BH * (Lk / P1_CHUNK), P1_THREADS>>>(k, v, d1);
    pass2_kernel<<<BH * (Lk / P2_ROWS), P2_THREADS>>>(q, out, d1);
}

// round 5
// speedup vs baseline: 1.5014x; 1.0030x over previous
#include <cuda_runtime.h>

// Shapes (fixed)
#define Bk 8
#define Lk 4096
#define Hk 16
#define Ek 64
#define BH (Bk*Hk)          // 128
#define RS (Hk*Ek)          // 1024 floats between consecutive l

// Scratch (no allocations allowed)
__device__ __align__(16) float g_kv[BH*Ek*Ek];    // 2 MB
__device__ __align__(16) float g_ksum[BH*Ek];     // 32 KB

typedef unsigned long long ull;

__device__ __forceinline__ ull pack2(float lo, float hi){
    ull r; asm("mov.b64 %0,{%1,%2};" : "=l"(r) : "f"(lo), "f"(hi)); return r;
}
__device__ __forceinline__ float2 unpk2(ull v){
    float2 r; asm("mov.b64 {%0,%1},%2;" : "=f"(r.x), "=f"(r.y) : "l"(v)); return r;
}
__device__ __forceinline__ ull fma2(ull a, ull b, ull c){
    ull d; asm("fma.rn.f32x2 %0,%1,%2,%3;" : "=l"(d) : "l"(a), "l"(b), "l"(c)); return d;
}
__device__ __forceinline__ float ex2(float x){
    float y; asm("ex2.approx.f32 %0,%1;" : "=f"(y) : "f"(x)); return y;
}

// ---------------------------------------------------------------------------
// Zero scratch each launch (graph replays!)
// ---------------------------------------------------------------------------
__global__ void zero_kernel(){
    int i = blockIdx.x*blockDim.x + threadIdx.x;
    float4 z = make_float4(0.f,0.f,0.f,0.f);
    if (i < BH*Ek*Ek/4) ((float4*)g_kv)[i] = z;
    if (i < BH*Ek/4)    ((float4*)g_ksum)[i] = z;
}

// ---------------------------------------------------------------------------
// Pass 1: k-softmax + KV / ksum accumulation.
// grid = 128 bh * 16 chunks = 2048 blocks, 128 threads.
// Warp-per-row softmax into shared; register tile 4e x 8d per thread:
// 3 LDS.128 per 16 fma2.
// ---------------------------------------------------------------------------
#define P1_THREADS 128
#define P1_TILE 16
#define P1_CHUNK 256

__global__ __launch_bounds__(P1_THREADS)
void pass1_kernel(const float* __restrict__ kin, const float* __restrict__ vin,
                  const float* __restrict__ dp)
{
    __shared__ float ks[P1_TILE][Ek];
    __shared__ float vs[P1_TILE][Ek];

    const int tid  = threadIdx.x;
    const int lane = tid & 31;
    const int warp = tid >> 5;
    const int blk  = blockIdx.x;
    const int bh    = blk >> 4;
    const int chunk = blk & 15;
    const int b = bh >> 4, h = bh & 15;
    const long base_bh = (long)b * Lk * RS + (long)h * Ek;
    const int l0 = chunk * P1_CHUNK;

    const float d1   = dp[0];
    const float temp = log1pf(__expf(d1));             // softplus(delta1)
    const float c    = 1.44269504088896340736f / temp; // log2(e)/temp

    const int e0 = (tid & 15) * 4;   // 16 e-groups of 4
    const int d0 = (tid >> 4) * 8;   // 8 d-groups of 8

    ull acc[16];
    #pragma unroll
    for (int j = 0; j < 16; j++) acc[j] = 0ULL;
    float2 lks = make_float2(0.f, 0.f);

    for (int t = 0; t < P1_CHUNK / P1_TILE; t++) {
        __syncthreads();
        // stage 16 rows: warp w handles rows 4w..4w+3
        #pragma unroll
        for (int i = 0; i < 4; i++) {
            const int rloc = warp * 4 + i;
            const int l = l0 + t * P1_TILE + rloc;
            float2 kk = ((const float2*)(kin + base_bh + (long)l * RS))[lane];
            float2 vv = ((const float2*)(vin + base_bh + (long)l * RS))[lane];
            float x0 = kk.x < 0.f ? -20.f : kk.x;
            float x1 = kk.y < 0.f ? -20.f : kk.y;
            float q0 = ex2(x0 * c), q1 = ex2(x1 * c);
            float s = q0 + q1;
            #pragma unroll
            for (int o = 16; o > 0; o >>= 1) s += __shfl_xor_sync(0xffffffffu, s, o);
            float rinv = 1.f / s;
            q0 *= rinv; q1 *= rinv;
            *(float2*)&ks[rloc][2*lane] = make_float2(q0, q1);
            *(float2*)&vs[rloc][2*lane] = vv;
            lks.x += q0; lks.y += q1;
        }
        __syncthreads();
        // accumulate 16 rows: per row, 4e x 8d register tile
        #pragma unroll
        for (int r = 0; r < P1_TILE; r++) {
            float4 a = *(const float4*)&ks[r][e0];
            ulonglong2 b0 = ((const ulonglong2*)&vs[r][d0])[0];
            ulonglong2 b1 = ((const ulonglong2*)&vs[r][d0])[1];
            ull ea;
            ea = pack2(a.x, a.x);
            acc[0]  = fma2(ea, b0.x, acc[0]);  acc[1]  = fma2(ea, b0.y, acc[1]);
            acc[2]  = fma2(ea, b1.x, acc[2]);  acc[3]  = fma2(ea, b1.y, acc[3]);
            ea = pack2(a.y, a.y);
            acc[4]  = fma2(ea, b0.x, acc[4]);  acc[5]  = fma2(ea, b0.y, acc[5]);
            acc[6]  = fma2(ea, b1.x, acc[6]);  acc[7]  = fma2(ea, b1.y, acc[7]);
            ea = pack2(a.z, a.z);
            acc[8]  = fma2(ea, b0.x, acc[8]);  acc[9]  = fma2(ea, b0.y, acc[9]);
            acc[10] = fma2(ea, b1.x, acc[10]); acc[11] = fma2(ea, b1.y, acc[11]);
            ea = pack2(a.w, a.w);
            acc[12] = fma2(ea, b0.x, acc[12]); acc[13] = fma2(ea, b0.y, acc[13]);
            acc[14] = fma2(ea, b1.x, acc[14]); acc[15] = fma2(ea, b1.y, acc[15]);
        }
    }

    float* kvdst = g_kv + (long)bh * Ek * Ek;
    #pragma unroll
    for (int e = 0; e < 4; e++) {
        #pragma unroll
        for (int j = 0; j < 4; j++) {
            float2 p = unpk2(acc[e*4 + j]);
            atomicAdd(&kvdst[(e0+e)*Ek + d0 + 2*j    ], p.x);
            atomicAdd(&kvdst[(e0+e)*Ek + d0 + 2*j + 1], p.y);
        }
    }
    atomicAdd(&g_ksum[bh*Ek + 2*lane],     lks.x);
    atomicAdd(&g_ksum[bh*Ek + 2*lane + 1], lks.y);
}

// ---------------------------------------------------------------------------
// Pass 2: q-softmax numerator + out = (eq @ KV) / (eq.ksum + eps*sq).
// grid = 128 bh * 64 chunks = 8192 blocks, 128 threads, 64 rows per block.
// Softmax: half-row per thread, pair combine via shfl. GEMM: 4 rows x 8 cols
// register tile per thread, eq transposed in smem (stride 68, aligned).
// ---------------------------------------------------------------------------
#define P2_THREADS 128
#define P2_ROWS 64
#define EQT_S 68

__global__ __launch_bounds__(P2_THREADS)
void pass2_kernel(const float* __restrict__ qin, float* __restrict__ out,
                  const float* __restrict__ dp)
{
    __shared__ float kvs[Ek][Ek];       // 16 KB
    __shared__ float eqT[Ek][EQT_S];    // 17.4 KB
    __shared__ float kss[Ek];
    __shared__ float invs[P2_ROWS];

    const int tid = threadIdx.x;
    const int blk = blockIdx.x;
    const int bh    = blk >> 6;
    const int chunk = blk & 63;
    const int b = bh >> 4, h = bh & 15;

    // load KV + ksum
    {
        const float4* src = (const float4*)(g_kv + (long)bh * Ek * Ek);
        float4* dst = (float4*)kvs;
        #pragma unroll
        for (int j = 0; j < 8; j++) dst[tid + j*128] = src[tid + j*128];
        if (tid < 16) ((float4*)kss)[tid] = ((const float4*)(g_ksum + bh*Ek))[tid];
    }
    const float d1   = dp[0];
    const float temp = log1pf(__expf(d1));
    const float c    = 1.44269504088896340736f / temp;
    __syncthreads();

    // softmax numerator: half-row per thread (row = tid>>1, half = tid&1)
    {
        const int lrow = tid >> 1;
        const int hh   = tid & 1;
        const int l = chunk * P2_ROWS + lrow;
        const float4* qrow = (const float4*)(qin + ((long)b*Lk + l)*RS + h*Ek + hh*32);
        float sq = 0.f, dn = 0.f;
        #pragma unroll
        for (int j = 0; j < 8; j++) {
            float4 qv = qrow[j];
            int e = hh*32 + 4*j;
            float v0 = ex2((qv.x < 0.f ? -20.f : qv.x) * c);
            float v1 = ex2((qv.y < 0.f ? -20.f : qv.y) * c);
            float v2 = ex2((qv.z < 0.f ? -20.f : qv.z) * c);
            float v3 = ex2((qv.w < 0.f ? -20.f : qv.w) * c);
            eqT[e  ][lrow] = v0;
            eqT[e+1][lrow] = v1;
            eqT[e+2][lrow] = v2;
            eqT[e+3][lrow] = v3;
            sq += v0 + v1 + v2 + v3;
            dn += v0*kss[e] + v1*kss[e+1] + v2*kss[e+2] + v3*kss[e+3];
        }
        sq += __shfl_xor_sync(0xffffffffu, sq, 1);
        dn += __shfl_xor_sync(0xffffffffu, dn, 1);
        if (hh == 0) invs[lrow] = 1.f / (dn + 1e-6f * sq);
    }
    __syncthreads();

    // GEMM: out[64 rows][64 cols], thread tile 4 rows x 8 cols
    const int r0 = (tid >> 3) * 4;   // 16 row-groups of 4
    const int c0 = (tid & 7) * 8;    // 8 col-groups of 8

    ull acc[16];
    #pragma unroll
    for (int j = 0; j < 16; j++) acc[j] = 0ULL;

    #pragma unroll 8
    for (int e = 0; e < Ek; e++) {
        float4 a = *(const float4*)&eqT[e][r0];
        ulonglong2 b0 = ((const ulonglong2*)&kvs[e][c0])[0];
        ulonglong2 b1 = ((const ulonglong2*)&kvs[e][c0])[1];
        ull ea;
        ea = pack2(a.x, a.x);
        acc[0]  = fma2(ea, b0.x, acc[0]);  acc[1]  = fma2(ea, b0.y, acc[1]);
        acc[2]  = fma2(ea, b1.x, acc[2]);  acc[3]  = fma2(ea, b1.y, acc[3]);
        ea = pack2(a.y, a.y);
        acc[4]  = fma2(ea, b0.x, acc[4]);  acc[5]  = fma2(ea, b0.y, acc[5]);
        acc[6]  = fma2(ea, b1.x, acc[6]);  acc[7]  = fma2(ea, b1.y, acc[7]);
        ea = pack2(a.z, a.z);
        acc[8]  = fma2(ea, b0.x, acc[8]);  acc[9]  = fma2(ea, b0.y, acc[9]);
        acc[10] = fma2(ea, b1.x, acc[10]); acc[11] = fma2(ea, b1.y, acc[11]);
        ea = pack2(a.w, a.w);
        acc[12] = fma2(ea, b0.x, acc[12]); acc[13] = fma2(ea, b0.y, acc[13]);
        acc[14] = fma2(ea, b1.x, acc[14]); acc[15] = fma2(ea, b1.y, acc[15]);
    }

    // epilogue: scale + store (coalesced: 8 lanes cover one 256B row span)
    #pragma unroll
    for (int r = 0; r < 4; r++) {
        const int lr = chunk * P2_ROWS + r0 + r;
        const float iv = invs[r0 + r];
        float* orow = out + ((long)b*Lk + lr)*RS + h*Ek + c0;
        float2 p0 = unpk2(acc[r*4 + 0]);
        float2 p1 = unpk2(acc[r*4 + 1]);
        float2 p2 = unpk2(acc[r*4 + 2]);
        float2 p3 = unpk2(acc[r*4 + 3]);
        ((float4*)orow)[0] = make_float4(p0.x*iv, p0.y*iv, p1.x*iv, p1.y*iv);
        ((float4*)orow)[1] = make_float4(p2.x*iv, p2.y*iv, p3.x*iv, p3.y*iv);
    }
}

// ---------------------------------------------------------------------------
extern "C" void kernel_launch(void* const* d_in, const int* in_sizes, int n_in,
                              void* d_out, int out_size)
{
    const float* q  = (const float*)d_in[0];
    const float* k  = (const float*)d_in[1];
    const float* v  = (const float*)d_in[2];
    const float* d1 = (const float*)d_in[3];
    float* out = (float*)d_out;

    zero_kernel<<<512, 256>>>();
    pass1_kernel<<<BH * (Lk / P1_CHUNK), P1_THREADS>>>(k, v, d1);
    pass2_kernel<<<BH * (Lk / P2_ROWS), P2_THREADS>>>(q, out, d1);
}